// round 2
// baseline (speedup 1.0000x reference)
#include <cuda_runtime.h>
#include <cuda_bf16.h>
#include <cstddef>

// ---------------------------------------------------------------------------
// StockPredictor: 2-layer LSTM (B=256, T=2048, D=1, H1=128, H2=64) + FC head.
// Strategy: persistent blocks, 2 batch elements per block, all weights on-SM
// in fp32 (layer1 W_hh1 split smem/registers), two sequential kernels
// communicating h1[B][T][H1] via a __device__ global scratch buffer.
// ---------------------------------------------------------------------------

constexpr int T  = 2048;
constexpr int B  = 256;
constexpr int H1 = 128;
constexpr int G1 = 4 * H1;   // 512
constexpr int H2 = 64;
constexpr int G2 = 4 * H2;   // 256
constexpr int BB = 2;        // batch elems per block
constexpr int NBLK = B / BB; // 128 blocks

// Layer-1 weight split
constexpr int W1S_COLS  = 96;    // cols [0,96) of W_hh1 live in smem
constexpr int W1S_PITCH = 100;   // 25*16B (odd) -> conflict-free LDS.128
constexpr int W1_REG    = 32;    // cols [96,128) live in registers

// Layer-2 smem pitches (odd multiples of 16B)
constexpr int W2A_PITCH = 132;   // W_ih2 rows of 128, padded
constexpr int W2B_PITCH = 68;    // W_hh2 rows of 64, padded

// smem sizes (floats)
constexpr int SMEM1_F = G1 * W1S_PITCH + BB * T + BB * H1 + BB * G1; // 56576
constexpr int SMEM2_F = G2 * W2A_PITCH + G2 * W2B_PITCH + 2 * BB * H1 + BB * H2 + BB * G2; // 52352
constexpr size_t SMEM1_B = SMEM1_F * sizeof(float); // 226304 B
constexpr size_t SMEM2_B = SMEM2_F * sizeof(float); // 209408 B

// scratch: h1 sequence, fp32  (256 MB)
__device__ float g_h1seq[(size_t)B * T * H1];

__device__ __forceinline__ float sigmoid_fast(float x) {
    return __fdividef(1.0f, 1.0f + __expf(-x));
}
__device__ __forceinline__ float tanh_acc(float x) {
    // 2*sigmoid(2x) - 1 : absolute error ~2e-7 (abs error is what propagates)
    return fmaf(2.0f, sigmoid_fast(2.0f * x), -1.0f);
}

// ---------------------------------------------------------------------------
// Layer 1: 512 threads, thread j owns gate row j of W_hh1.
// ---------------------------------------------------------------------------
__global__ __launch_bounds__(512, 1)
void lstm1_kernel(const float* __restrict__ x,
                  const float* __restrict__ W_ih1,
                  const float* __restrict__ W_hh1,
                  const float* __restrict__ b_ih1,
                  const float* __restrict__ b_hh1)
{
    extern __shared__ float sm[];
    float* Ws = sm;                       // [512][W1S_PITCH]
    float* xs = Ws + G1 * W1S_PITCH;      // [BB][T]
    float* hs = xs + BB * T;              // [BB][H1]
    float* gs = hs + BB * H1;             // [BB][G1] activated gates

    const int tid = threadIdx.x;
    const int b0  = blockIdx.x * BB;

    // --- load weights: smem part (cols [0,96)) ---
    for (int i = tid; i < G1 * W1S_COLS; i += 512) {
        int r = i / W1S_COLS;
        int c = i - r * W1S_COLS;
        Ws[r * W1S_PITCH + c] = W_hh1[r * H1 + c];
    }
    // --- register part (cols [96,128)) ---
    float wreg[W1_REG];
    #pragma unroll
    for (int c = 0; c < W1_REG; c++)
        wreg[c] = W_hh1[tid * H1 + W1S_COLS + c];

    const float wx   = W_ih1[tid];               // [512][1]
    const float bias = b_ih1[tid] + b_hh1[tid];

    // --- stage x for both batch elements (rows are adjacent) ---
    for (int i = tid; i < BB * T; i += 512)
        xs[i] = x[(size_t)b0 * T + i];

    if (tid < BB * H1) hs[tid] = 0.0f;
    __syncthreads();

    float c_state = 0.0f;  // valid for tid < 256 (bb = tid>>7, m = tid&127)

    const float* wrow = Ws + tid * W1S_PITCH;
    const float4* w4  = reinterpret_cast<const float4*>(wrow);
    const float4* h04 = reinterpret_cast<const float4*>(hs);
    const float4* h14 = reinterpret_cast<const float4*>(hs + H1);

    for (int t = 0; t < T; t++) {
        float acc0 = fmaf(xs[t],     wx, bias);
        float acc1 = fmaf(xs[T + t], wx, bias);

        #pragma unroll
        for (int k4 = 0; k4 < W1S_COLS / 4; k4++) {
            float4 w = w4[k4];
            float4 a = h04[k4];
            float4 b = h14[k4];
            acc0 = fmaf(w.x, a.x, acc0); acc0 = fmaf(w.y, a.y, acc0);
            acc0 = fmaf(w.z, a.z, acc0); acc0 = fmaf(w.w, a.w, acc0);
            acc1 = fmaf(w.x, b.x, acc1); acc1 = fmaf(w.y, b.y, acc1);
            acc1 = fmaf(w.z, b.z, acc1); acc1 = fmaf(w.w, b.w, acc1);
        }
        #pragma unroll
        for (int k4 = 0; k4 < W1_REG / 4; k4++) {
            float4 a = h04[W1S_COLS / 4 + k4];
            float4 b = h14[W1S_COLS / 4 + k4];
            int k = 4 * k4;
            acc0 = fmaf(wreg[k],   a.x, acc0); acc0 = fmaf(wreg[k+1], a.y, acc0);
            acc0 = fmaf(wreg[k+2], a.z, acc0); acc0 = fmaf(wreg[k+3], a.w, acc0);
            acc1 = fmaf(wreg[k],   b.x, acc1); acc1 = fmaf(wreg[k+1], b.y, acc1);
            acc1 = fmaf(wreg[k+2], b.z, acc1); acc1 = fmaf(wreg[k+3], b.w, acc1);
        }

        float a0, a1;
        if (tid >= 2 * H1 && tid < 3 * H1) {  // g gate -> tanh
            a0 = tanh_acc(acc0); a1 = tanh_acc(acc1);
        } else {                               // i, f, o -> sigmoid
            a0 = sigmoid_fast(acc0); a1 = sigmoid_fast(acc1);
        }
        gs[tid] = a0;
        gs[G1 + tid] = a1;
        __syncthreads();

        if (tid < BB * H1) {
            int bb = tid >> 7;
            int m  = tid & (H1 - 1);
            const float* gb = gs + bb * G1;
            float i_ = gb[m];
            float f_ = gb[H1 + m];
            float g_ = gb[2 * H1 + m];
            float o_ = gb[3 * H1 + m];
            c_state  = fmaf(f_, c_state, i_ * g_);
            float h  = o_ * tanh_acc(c_state);
            hs[tid]  = h;
            g_h1seq[((size_t)(b0 + bb) * T + t) * H1 + m] = h;
        }
        __syncthreads();
    }
}

// ---------------------------------------------------------------------------
// Layer 2 + FC head: 256 threads, thread j owns gate row j.
// ---------------------------------------------------------------------------
__global__ __launch_bounds__(256, 1)
void lstm2_kernel(const float* __restrict__ W_ih2,
                  const float* __restrict__ W_hh2,
                  const float* __restrict__ b_ih2,
                  const float* __restrict__ b_hh2,
                  const float* __restrict__ W_fc1,
                  const float* __restrict__ b_fc1,
                  const float* __restrict__ W_fc2,
                  const float* __restrict__ b_fc2,
                  float* __restrict__ out)
{
    extern __shared__ float sm[];
    float* Wa  = sm;                          // [256][W2A_PITCH]
    float* Wb  = Wa + G2 * W2A_PITCH;         // [256][W2B_PITCH]
    float* h1s = Wb + G2 * W2B_PITCH;         // [2][BB][H1] double buffer
    float* h2s = h1s + 2 * BB * H1;           // [BB][H2]
    float* gs  = h2s + BB * H2;               // [BB][G2]

    const int tid = threadIdx.x;
    const int b0  = blockIdx.x * BB;

    for (int i = tid; i < G2 * H1; i += 256) {
        int r = i >> 7, c = i & (H1 - 1);
        Wa[r * W2A_PITCH + c] = W_ih2[i];
    }
    for (int i = tid; i < G2 * H2; i += 256) {
        int r = i >> 6, c = i & (H2 - 1);
        Wb[r * W2B_PITCH + c] = W_hh2[i];
    }
    const float bias = b_ih2[tid] + b_hh2[tid];

    if (tid < BB * H2) h2s[tid] = 0.0f;
    // preload h1 for t=0
    {
        int bb = tid >> 7, m = tid & (H1 - 1);
        h1s[tid] = g_h1seq[((size_t)(b0 + bb) * T + 0) * H1 + m];
    }
    __syncthreads();

    float c_state = 0.0f;  // valid for tid < 128 (bb = tid>>6, m = tid&63)

    const float4* wa4 = reinterpret_cast<const float4*>(Wa + tid * W2A_PITCH);
    const float4* wb4 = reinterpret_cast<const float4*>(Wb + tid * W2B_PITCH);
    const float4* h24a = reinterpret_cast<const float4*>(h2s);
    const float4* h24b = reinterpret_cast<const float4*>(h2s + H2);

    const int ld_bb = tid >> 7;
    const int ld_m  = tid & (H1 - 1);

    for (int t = 0; t < T; t++) {
        const int cur = t & 1;
        const int nxt = cur ^ 1;
        // prefetch next step's h1 into the other buffer
        if (t + 1 < T)
            h1s[nxt * BB * H1 + tid] =
                g_h1seq[((size_t)(b0 + ld_bb) * T + (t + 1)) * H1 + ld_m];

        const float4* h14a = reinterpret_cast<const float4*>(h1s + cur * BB * H1);
        const float4* h14b = reinterpret_cast<const float4*>(h1s + cur * BB * H1 + H1);

        float acc0 = bias, acc1 = bias;
        #pragma unroll
        for (int k4 = 0; k4 < H1 / 4; k4++) {
            float4 w = wa4[k4];
            float4 a = h14a[k4];
            float4 b = h14b[k4];
            acc0 = fmaf(w.x, a.x, acc0); acc0 = fmaf(w.y, a.y, acc0);
            acc0 = fmaf(w.z, a.z, acc0); acc0 = fmaf(w.w, a.w, acc0);
            acc1 = fmaf(w.x, b.x, acc1); acc1 = fmaf(w.y, b.y, acc1);
            acc1 = fmaf(w.z, b.z, acc1); acc1 = fmaf(w.w, b.w, acc1);
        }
        #pragma unroll
        for (int k4 = 0; k4 < H2 / 4; k4++) {
            float4 w = wb4[k4];
            float4 a = h24a[k4];
            float4 b = h24b[k4];
            acc0 = fmaf(w.x, a.x, acc0); acc0 = fmaf(w.y, a.y, acc0);
            acc0 = fmaf(w.z, a.z, acc0); acc0 = fmaf(w.w, a.w, acc0);
            acc1 = fmaf(w.x, b.x, acc1); acc1 = fmaf(w.y, b.y, acc1);
            acc1 = fmaf(w.z, b.z, acc1); acc1 = fmaf(w.w, b.w, acc1);
        }

        float a0, a1;
        if (tid >= 2 * H2 && tid < 3 * H2) {
            a0 = tanh_acc(acc0); a1 = tanh_acc(acc1);
        } else {
            a0 = sigmoid_fast(acc0); a1 = sigmoid_fast(acc1);
        }
        gs[tid] = a0;
        gs[G2 + tid] = a1;
        __syncthreads();

        if (tid < BB * H2) {
            int bb = tid >> 6;
            int m  = tid & (H2 - 1);
            const float* gb = gs + bb * G2;
            float i_ = gb[m];
            float f_ = gb[H2 + m];
            float g_ = gb[2 * H2 + m];
            float o_ = gb[3 * H2 + m];
            c_state  = fmaf(f_, c_state, i_ * g_);
            h2s[tid] = o_ * tanh_acc(c_state);
        }
        __syncthreads();
    }

    // ---- FC head on final h2: [BB][64] -> [BB][25] -> [BB][1] ----
    if (tid < BB * 25) {
        int bb = tid / 25;
        int i  = tid - bb * 25;
        float a = b_fc1[i];
        #pragma unroll
        for (int k = 0; k < H2; k++)
            a = fmaf(W_fc1[i * H2 + k], h2s[bb * H2 + k], a);
        gs[bb * 32 + i] = a;  // reuse gs as staging
    }
    __syncthreads();
    if (tid < BB) {
        float a = b_fc2[0];
        #pragma unroll
        for (int i = 0; i < 25; i++)
            a = fmaf(W_fc2[i], gs[tid * 32 + i], a);
        out[b0 + tid] = a;
    }
}

// ---------------------------------------------------------------------------
extern "C" void kernel_launch(void* const* d_in, const int* in_sizes, int n_in,
                              void* d_out, int out_size)
{
    const float* x     = (const float*)d_in[0];
    const float* W_ih1 = (const float*)d_in[1];
    const float* W_hh1 = (const float*)d_in[2];
    const float* b_ih1 = (const float*)d_in[3];
    const float* b_hh1 = (const float*)d_in[4];
    const float* W_ih2 = (const float*)d_in[5];
    const float* W_hh2 = (const float*)d_in[6];
    const float* b_ih2 = (const float*)d_in[7];
    const float* b_hh2 = (const float*)d_in[8];
    const float* W_fc1 = (const float*)d_in[9];
    const float* b_fc1 = (const float*)d_in[10];
    const float* W_fc2 = (const float*)d_in[11];
    const float* b_fc2 = (const float*)d_in[12];
    float* out = (float*)d_out;

    static bool attr_done = false;
    if (!attr_done) {
        cudaFuncSetAttribute(lstm1_kernel,
                             cudaFuncAttributeMaxDynamicSharedMemorySize, (int)SMEM1_B);
        cudaFuncSetAttribute(lstm2_kernel,
                             cudaFuncAttributeMaxDynamicSharedMemorySize, (int)SMEM2_B);
        attr_done = true;
    }

    lstm1_kernel<<<NBLK, 512, SMEM1_B>>>(x, W_ih1, W_hh1, b_ih1, b_hh1);
    lstm2_kernel<<<NBLK, 256, SMEM2_B>>>(W_ih2, W_hh2, b_ih2, b_hh2,
                                         W_fc1, b_fc1, W_fc2, b_fc2, out);
}

// round 3
// speedup vs baseline: 1.4016x; 1.4016x over previous
#include <cuda_runtime.h>
#include <cuda_bf16.h>
#include <cstddef>

// ---------------------------------------------------------------------------
// StockPredictor: 2-layer LSTM (B=256, T=2048, D=1, H1=128, H2=64) + FC head.
// R2: packed f32x2 FMAs, layer1 weights half-regs/half-smem, layer2 weights
// fully register-resident with 2-way K split.
// ---------------------------------------------------------------------------

constexpr int T  = 2048;
constexpr int B  = 256;
constexpr int H1 = 128;
constexpr int G1 = 4 * H1;   // 512
constexpr int H2 = 64;
constexpr int G2 = 4 * H2;   // 256
constexpr int BB = 2;        // batch elems per block
constexpr int NBLK = B / BB; // 128 blocks

// Layer-1 weight split: cols [0,64) in smem, cols [64,128) in registers
constexpr int W1S_COLS  = 64;
constexpr int W1S_PITCH = 68;    // 17*16B (odd) -> conflict-free LDS.128

constexpr int SMEM1_F = G1 * W1S_PITCH + BB * T + BB * H1 + BB * G1; // 40192
constexpr size_t SMEM1_B = SMEM1_F * sizeof(float);                  // 160768 B

// Layer-2 smem: h1 double buffer + h2 + partials + gates
constexpr int SMEM2_F = 2 * BB * H1 + BB * H2 + 2 * G2 + BB * G2;    // 1664
constexpr size_t SMEM2_B = SMEM2_F * sizeof(float);                  // 6656 B

// scratch: h1 sequence, fp32  (256 MB)
__device__ float g_h1seq[(size_t)B * T * H1];

// ---------------------------------------------------------------------------
__device__ __forceinline__ void fma2(unsigned long long& acc,
                                     unsigned long long a,
                                     unsigned long long b) {
    asm("fma.rn.f32x2 %0, %1, %2, %0;" : "+l"(acc) : "l"(a), "l"(b));
}
__device__ __forceinline__ float f32x2_sum2(unsigned long long u,
                                            unsigned long long v) {
    unsigned long long s;
    asm("add.rn.f32x2 %0, %1, %2;" : "=l"(s) : "l"(u), "l"(v));
    float lo, hi;
    asm("mov.b64 {%0, %1}, %2;" : "=f"(lo), "=f"(hi) : "l"(s));
    return lo + hi;
}
__device__ __forceinline__ float sigmoid_fast(float x) {
    return __fdividef(1.0f, 1.0f + __expf(-x));
}
__device__ __forceinline__ float tanh_acc(float x) {
    return fmaf(2.0f, sigmoid_fast(2.0f * x), -1.0f);
}

// ---------------------------------------------------------------------------
// Layer 1: 512 threads, thread j owns gate row j of W_hh1 (full K=128).
// ---------------------------------------------------------------------------
__global__ __launch_bounds__(512, 1)
void lstm1_kernel(const float* __restrict__ x,
                  const float* __restrict__ W_ih1,
                  const float* __restrict__ W_hh1,
                  const float* __restrict__ b_ih1,
                  const float* __restrict__ b_hh1)
{
    extern __shared__ float sm[];
    float* Ws = sm;                       // [512][W1S_PITCH], cols [0,64)
    float* xs = Ws + G1 * W1S_PITCH;      // [BB][T]
    float* hs = xs + BB * T;              // [BB][H1]
    float* gs = hs + BB * H1;             // [BB][G1] activated gates

    const int tid   = threadIdx.x;
    const int bbase = blockIdx.x * BB;

    // smem weights: cols [0,64)
    for (int i = tid; i < G1 * W1S_COLS; i += 512) {
        int r = i >> 6;
        int c = i & 63;
        Ws[r * W1S_PITCH + c] = W_hh1[r * H1 + c];
    }
    // reg weights: cols [64,128), 64 floats = 16 ulonglong2 (each holds 2 f32x2)
    ulonglong2 wr2[16];
    {
        const ulonglong2* wsrc =
            reinterpret_cast<const ulonglong2*>(W_hh1 + tid * H1 + W1S_COLS);
        #pragma unroll
        for (int j = 0; j < 16; j++) wr2[j] = wsrc[j];
    }

    const float wx   = W_ih1[tid];
    const float bias = b_ih1[tid] + b_hh1[tid];

    for (int i = tid; i < BB * T; i += 512)
        xs[i] = x[(size_t)bbase * T + i];
    if (tid < BB * H1) hs[tid] = 0.0f;
    __syncthreads();

    float c_state = 0.0f;  // valid for tid < 256

    const ulonglong2* w2  = reinterpret_cast<const ulonglong2*>(Ws + tid * W1S_PITCH);
    const ulonglong2* ha2 = reinterpret_cast<const ulonglong2*>(hs);
    const ulonglong2* hb2 = reinterpret_cast<const ulonglong2*>(hs + H1);

    for (int t = 0; t < T; t++) {
        // 4 packed accumulator chains: {batch0,batch1} x {even-odd split}
        unsigned long long a0 = 0, a1 = 0, c0 = 0, c1 = 0;

        #pragma unroll
        for (int i = 0; i < 16; i++) {   // smem-weight part, cols [0,64)
            ulonglong2 w = w2[i];
            ulonglong2 p = ha2[i];
            ulonglong2 q = hb2[i];
            fma2(a0, w.x, p.x); fma2(a1, w.y, p.y);
            fma2(c0, w.x, q.x); fma2(c1, w.y, q.y);
        }
        #pragma unroll
        for (int i = 0; i < 16; i++) {   // reg-weight part, cols [64,128)
            ulonglong2 w = wr2[i];
            ulonglong2 p = ha2[16 + i];
            ulonglong2 q = hb2[16 + i];
            fma2(a0, w.x, p.x); fma2(a1, w.y, p.y);
            fma2(c0, w.x, q.x); fma2(c1, w.y, q.y);
        }

        float acc0 = fmaf(xs[t],     wx, bias) + f32x2_sum2(a0, a1);
        float acc1 = fmaf(xs[T + t], wx, bias) + f32x2_sum2(c0, c1);

        float v0, v1;
        if (tid >= 2 * H1 && tid < 3 * H1) {       // g gate (warps 8-11, uniform)
            v0 = tanh_acc(acc0); v1 = tanh_acc(acc1);
        } else {                                   // i, f, o
            v0 = sigmoid_fast(acc0); v1 = sigmoid_fast(acc1);
        }
        gs[tid]      = v0;
        gs[G1 + tid] = v1;
        __syncthreads();

        if (tid < BB * H1) {
            int bb = tid >> 7;
            int m  = tid & (H1 - 1);
            const float* gb = gs + bb * G1;
            float i_ = gb[m];
            float f_ = gb[H1 + m];
            float g_ = gb[2 * H1 + m];
            float o_ = gb[3 * H1 + m];
            c_state  = fmaf(f_, c_state, i_ * g_);
            float h  = o_ * tanh_acc(c_state);
            hs[tid]  = h;
            __stcs(&g_h1seq[((size_t)(bbase + bb) * T + t) * H1 + m], h);
        }
        __syncthreads();
    }
}

// ---------------------------------------------------------------------------
// Layer 2 + FC head: 512 threads. r = tid&255 gate row, part = tid>>8.
// part0: K = h1[0:96).  part1: K = h1[96:128) + h2[0:64).
// All weights register-resident (96 floats = 24 ulonglong2 per thread).
// ---------------------------------------------------------------------------
__global__ __launch_bounds__(512, 1)
void lstm2_kernel(const float* __restrict__ W_ih2,
                  const float* __restrict__ W_hh2,
                  const float* __restrict__ b_ih2,
                  const float* __restrict__ b_hh2,
                  const float* __restrict__ W_fc1,
                  const float* __restrict__ b_fc1,
                  const float* __restrict__ W_fc2,
                  const float* __restrict__ b_fc2,
                  float* __restrict__ out)
{
    extern __shared__ float sm[];
    float* h1s = sm;                 // [2][BB][H1] double buffer   (512)
    float* h2s = h1s + 2 * BB * H1;  // [BB][H2]                    (128)
    float* ps  = h2s + BB * H2;      // [G2][2] partials            (512)
    float* gs  = ps + 2 * G2;        // [BB][G2] activated gates    (512)

    const int tid   = threadIdx.x;
    const int r     = tid & (G2 - 1);
    const int part  = tid >> 8;
    const int bbase = blockIdx.x * BB;

    // register weights
    ulonglong2 wr2[24];
    if (part == 0) {
        const ulonglong2* wsrc = reinterpret_cast<const ulonglong2*>(W_ih2 + r * H1);
        #pragma unroll
        for (int j = 0; j < 24; j++) wr2[j] = wsrc[j];
    } else {
        const ulonglong2* wa = reinterpret_cast<const ulonglong2*>(W_ih2 + r * H1 + 96);
        const ulonglong2* wb = reinterpret_cast<const ulonglong2*>(W_hh2 + r * H2);
        #pragma unroll
        for (int j = 0; j < 8; j++) wr2[j] = wa[j];
        #pragma unroll
        for (int j = 0; j < 16; j++) wr2[8 + j] = wb[j];
    }
    const float bias = (part == 0) ? (b_ih2[r] + b_hh2[r]) : 0.0f;

    if (tid < BB * H2) h2s[tid] = 0.0f;
    if (tid < BB * H1) {   // preload h1 for t=0 into buffer 0
        int bb = tid >> 7, m = tid & (H1 - 1);
        h1s[tid] = __ldcs(&g_h1seq[((size_t)(bbase + bb) * T + 0) * H1 + m]);
    }
    __syncthreads();

    float c_state = 0.0f;  // valid for tid < 128

    const int ld_bb = (tid >> 7) & 1;        // for part1 prefetch (tid-256)
    const int ld_m  = tid & (H1 - 1);
    float2* ps2 = reinterpret_cast<float2*>(ps);

    for (int t = 0; t < T; t++) {
        const int cur = t & 1;
        const float* h1c = h1s + cur * BB * H1;

        // part1 threads prefetch next step's h1 (registers), stored after FMA
        float pre = 0.0f;
        if (part == 1 && t + 1 < T)
            pre = __ldcs(&g_h1seq[((size_t)(bbase + ld_bb) * T + (t + 1)) * H1 + ld_m]);

        unsigned long long a0 = 0, a1 = 0, c0 = 0, c1 = 0;
        if (part == 0) {
            const ulonglong2* pa = reinterpret_cast<const ulonglong2*>(h1c);
            const ulonglong2* pb = reinterpret_cast<const ulonglong2*>(h1c + H1);
            #pragma unroll
            for (int i = 0; i < 24; i++) {
                ulonglong2 w = wr2[i];
                ulonglong2 p = pa[i];
                ulonglong2 q = pb[i];
                fma2(a0, w.x, p.x); fma2(a1, w.y, p.y);
                fma2(c0, w.x, q.x); fma2(c1, w.y, q.y);
            }
        } else {
            const ulonglong2* pa = reinterpret_cast<const ulonglong2*>(h1c + 96);
            const ulonglong2* pb = reinterpret_cast<const ulonglong2*>(h1c + H1 + 96);
            #pragma unroll
            for (int i = 0; i < 8; i++) {
                ulonglong2 w = wr2[i];
                ulonglong2 p = pa[i];
                ulonglong2 q = pb[i];
                fma2(a0, w.x, p.x); fma2(a1, w.y, p.y);
                fma2(c0, w.x, q.x); fma2(c1, w.y, q.y);
            }
            const ulonglong2* va = reinterpret_cast<const ulonglong2*>(h2s);
            const ulonglong2* vb = reinterpret_cast<const ulonglong2*>(h2s + H2);
            #pragma unroll
            for (int i = 0; i < 16; i++) {
                ulonglong2 w = wr2[8 + i];
                ulonglong2 p = va[i];
                ulonglong2 q = vb[i];
                fma2(a0, w.x, p.x); fma2(a1, w.y, p.y);
                fma2(c0, w.x, q.x); fma2(c1, w.y, q.y);
            }
        }
        float acc0 = bias + f32x2_sum2(a0, a1);
        float acc1 = bias + f32x2_sum2(c0, c1);

        if (part == 1) {
            ps2[r] = make_float2(acc0, acc1);
            // store prefetched h1 into the other buffer
            if (t + 1 < T) h1s[(cur ^ 1) * BB * H1 + (tid - G2)] = pre;
        }
        __syncthreads();

        if (part == 0) {
            float2 p = ps2[r];
            acc0 += p.x;
            acc1 += p.y;
            float v0, v1;
            if (r >= 2 * H2 && r < 3 * H2) {      // g gate (warps 4-5, uniform)
                v0 = tanh_acc(acc0); v1 = tanh_acc(acc1);
            } else {
                v0 = sigmoid_fast(acc0); v1 = sigmoid_fast(acc1);
            }
            gs[r]      = v0;
            gs[G2 + r] = v1;
        }
        __syncthreads();

        if (tid < BB * H2) {
            int bb = tid >> 6;
            int m  = tid & (H2 - 1);
            const float* gb = gs + bb * G2;
            float i_ = gb[m];
            float f_ = gb[H2 + m];
            float g_ = gb[2 * H2 + m];
            float o_ = gb[3 * H2 + m];
            c_state  = fmaf(f_, c_state, i_ * g_);
            h2s[tid] = o_ * tanh_acc(c_state);
        }
        __syncthreads();
    }

    // ---- FC head on final h2: [BB][64] -> [BB][25] -> [BB][1] ----
    if (tid < BB * 25) {
        int bb = tid / 25;
        int i  = tid - bb * 25;
        float a = b_fc1[i];
        #pragma unroll
        for (int k = 0; k < H2; k++)
            a = fmaf(W_fc1[i * H2 + k], h2s[bb * H2 + k], a);
        gs[bb * 32 + i] = a;
    }
    __syncthreads();
    if (tid < BB) {
        float a = b_fc2[0];
        #pragma unroll
        for (int i = 0; i < 25; i++)
            a = fmaf(W_fc2[i], gs[tid * 32 + i], a);
        out[bbase + tid] = a;
    }
}

// ---------------------------------------------------------------------------
extern "C" void kernel_launch(void* const* d_in, const int* in_sizes, int n_in,
                              void* d_out, int out_size)
{
    const float* x     = (const float*)d_in[0];
    const float* W_ih1 = (const float*)d_in[1];
    const float* W_hh1 = (const float*)d_in[2];
    const float* b_ih1 = (const float*)d_in[3];
    const float* b_hh1 = (const float*)d_in[4];
    const float* W_ih2 = (const float*)d_in[5];
    const float* W_hh2 = (const float*)d_in[6];
    const float* b_ih2 = (const float*)d_in[7];
    const float* b_hh2 = (const float*)d_in[8];
    const float* W_fc1 = (const float*)d_in[9];
    const float* b_fc1 = (const float*)d_in[10];
    const float* W_fc2 = (const float*)d_in[11];
    const float* b_fc2 = (const float*)d_in[12];
    float* out = (float*)d_out;

    static bool attr_done = false;
    if (!attr_done) {
        cudaFuncSetAttribute(lstm1_kernel,
                             cudaFuncAttributeMaxDynamicSharedMemorySize, (int)SMEM1_B);
        attr_done = true;
    }

    lstm1_kernel<<<NBLK, 512, SMEM1_B>>>(x, W_ih1, W_hh1, b_ih1, b_hh1);
    lstm2_kernel<<<NBLK, 512, SMEM2_B>>>(W_ih2, W_hh2, b_ih2, b_hh2,
                                         W_fc1, b_fc1, W_fc2, b_fc2, out);
}